// round 8
// baseline (speedup 1.0000x reference)
#include <cuda_runtime.h>
#include <cuda_bf16.h>
#include <math.h>

// Problem: b=2, f=8, c=64, h=w=256  (fp32)
//   k_sum[bf,c] = sum_{hw} nbr[bf,c,hw]
//   out[bf,hw]  = sigmoid( sum_c ref[bf,c,hw] * k_sum[bf,c] )
// HBM streaming: 2 x 268MB reads + 4MB write.
// R6 baseline: ksum 39.8us @6.74TB/s, weight 43.8us @6.21TB/s (8KB windows,
// __ldcs/__stcs, fast sigmoid). This round: per-block channel-start stagger
// to decorrelate the instantaneous DRAM footprint (lockstep blocks otherwise
// all hit the same 16 channel planes simultaneously).

#define BF     16          // b*f
#define C      64
#define HW     65536       // 256*256
#define HW4    16384       // HW / 4 (float4 units)

__device__ float g_ksum[BF * C];

// ---------------------------------------------------------------------------
// Kernel 1: per-channel-plane reduction. One block per (bf,c) plane (256 KB
// contiguous). ~6.74 TB/s measured — unchanged.
// ---------------------------------------------------------------------------
__global__ __launch_bounds__(256) void ksum_kernel(const float* __restrict__ nbr) {
    const int ch = blockIdx.x;                       // 0..1023 == bf*64 + c
    const float4* __restrict__ p =
        reinterpret_cast<const float4*>(nbr + (size_t)ch * HW);

    float s = 0.0f;
    #pragma unroll 8
    for (int i = threadIdx.x; i < HW4; i += 256) {
        float4 v = __ldcs(p + i);
        s += (v.x + v.y) + (v.z + v.w);
    }

    #pragma unroll
    for (int off = 16; off > 0; off >>= 1)
        s += __shfl_xor_sync(0xffffffffu, s, off);

    __shared__ float warp_sums[8];
    const int lane = threadIdx.x & 31;
    const int wid  = threadIdx.x >> 5;
    if (lane == 0) warp_sums[wid] = s;
    __syncthreads();

    if (wid == 0) {
        float t = (lane < 8) ? warp_sums[lane] : 0.0f;
        #pragma unroll
        for (int off = 4; off > 0; off >>= 1)
            t += __shfl_xor_sync(0xffffffffu, t, off);
        if (lane == 0) g_ksum[ch] = t;
    }
}

// ---------------------------------------------------------------------------
// Kernel 2: weighted channel contraction + sigmoid (R6 shape: best measured).
// 512 blocks x 256 threads, 2 float4/thread, 8 KB contiguous per channel step.
// NEW: channel iteration order staggered per block: ch = (c + 23*blockIdx)&63.
// Sum is commutative -> identical result; instantaneous DRAM footprint is now
// spread over all 64 planes instead of 1 per bf.
// ---------------------------------------------------------------------------
__global__ __launch_bounds__(256) void weight_kernel(const float* __restrict__ ref,
                                                     float* __restrict__ out) {
    const int bf  = blockIdx.x >> 5;                     // 32 blocks per bf
    const int win = (blockIdx.x & 31) << 9;              // window base (float4)
    const int p0  = win + threadIdx.x;
    const int p1  = p0 + 256;
    const int off = (blockIdx.x * 23) & (C - 1);         // channel stagger

    __shared__ float sk[C];
    if (threadIdx.x < C) sk[threadIdx.x] = g_ksum[bf * C + threadIdx.x];
    __syncthreads();

    const float4* __restrict__ base =
        reinterpret_cast<const float4*>(ref) + (size_t)bf * C * HW4;

    float a0x = 0.f, a0y = 0.f, a0z = 0.f, a0w = 0.f;
    float a1x = 0.f, a1y = 0.f, a1z = 0.f, a1w = 0.f;

    #pragma unroll
    for (int c = 0; c < C; c++) {
        const int ch = (c + off) & (C - 1);
        const float4* chp = base + (size_t)ch * HW4;
        float4 v0 = __ldcs(chp + p0);
        float4 v1 = __ldcs(chp + p1);
        float  k  = sk[ch];
        a0x = fmaf(v0.x, k, a0x);
        a0y = fmaf(v0.y, k, a0y);
        a0z = fmaf(v0.z, k, a0z);
        a0w = fmaf(v0.w, k, a0w);
        a1x = fmaf(v1.x, k, a1x);
        a1y = fmaf(v1.y, k, a1y);
        a1z = fmaf(v1.z, k, a1z);
        a1w = fmaf(v1.w, k, a1w);
    }

    float4 r0, r1;
    r0.x = __fdividef(1.0f, 1.0f + __expf(-a0x));
    r0.y = __fdividef(1.0f, 1.0f + __expf(-a0y));
    r0.z = __fdividef(1.0f, 1.0f + __expf(-a0z));
    r0.w = __fdividef(1.0f, 1.0f + __expf(-a0w));
    r1.x = __fdividef(1.0f, 1.0f + __expf(-a1x));
    r1.y = __fdividef(1.0f, 1.0f + __expf(-a1y));
    r1.z = __fdividef(1.0f, 1.0f + __expf(-a1z));
    r1.w = __fdividef(1.0f, 1.0f + __expf(-a1w));

    float4* o = reinterpret_cast<float4*>(out) + (size_t)bf * HW4;
    __stcs(o + p0, r0);
    __stcs(o + p1, r1);
}

// ---------------------------------------------------------------------------
extern "C" void kernel_launch(void* const* d_in, const int* in_sizes, int n_in,
                              void* d_out, int out_size) {
    const float* nbr = (const float*)d_in[0];
    const float* ref = (const float*)d_in[1];
    float* out = (float*)d_out;

    ksum_kernel<<<BF * C, 256>>>(nbr);
    weight_kernel<<<BF * HW4 / 512, 256>>>(ref, out);
}

// round 9
// speedup vs baseline: 1.0118x; 1.0118x over previous
#include <cuda_runtime.h>
#include <cuda_bf16.h>
#include <math.h>

// Problem: b=2, f=8, c=64, h=w=256  (fp32)
//   k_sum[bf,c] = sum_{hw} nbr[bf,c,hw]
//   out[bf,hw]  = sigmoid( sum_c ref[bf,c,hw] * k_sum[bf,c] )
// HBM streaming: 2 x 268MB reads + 4MB write.
// R6 best: weight @6.21TB/s with 8KB windows / 40% occ / compiler-batched
// __ldcs loop / __stcs / fast sigmoid. This round: same proven loop body at
// 86% occupancy (512x512, 1 float4/thread) — the one untested matrix cell.

#define BF     16          // b*f
#define C      64
#define HW     65536       // 256*256
#define HW4    16384       // HW / 4 (float4 units)

__device__ float g_ksum[BF * C];

// ---------------------------------------------------------------------------
// Kernel 1: per-channel-plane reduction. One block per (bf,c) plane (256 KB
// contiguous). ~6.74 TB/s measured — unchanged.
// ---------------------------------------------------------------------------
__global__ __launch_bounds__(256) void ksum_kernel(const float* __restrict__ nbr) {
    const int ch = blockIdx.x;                       // 0..1023 == bf*64 + c
    const float4* __restrict__ p =
        reinterpret_cast<const float4*>(nbr + (size_t)ch * HW);

    float s = 0.0f;
    #pragma unroll 8
    for (int i = threadIdx.x; i < HW4; i += 256) {
        float4 v = __ldcs(p + i);
        s += (v.x + v.y) + (v.z + v.w);
    }

    #pragma unroll
    for (int off = 16; off > 0; off >>= 1)
        s += __shfl_xor_sync(0xffffffffu, s, off);

    __shared__ float warp_sums[8];
    const int lane = threadIdx.x & 31;
    const int wid  = threadIdx.x >> 5;
    if (lane == 0) warp_sums[wid] = s;
    __syncthreads();

    if (wid == 0) {
        float t = (lane < 8) ? warp_sums[lane] : 0.0f;
        #pragma unroll
        for (int off = 4; off > 0; off >>= 1)
            t += __shfl_xor_sync(0xffffffffu, t, off);
        if (lane == 0) g_ksum[ch] = t;
    }
}

// ---------------------------------------------------------------------------
// Kernel 2: weighted channel contraction + sigmoid.
// 512 blocks x 512 threads, ONE float4 per thread -> still 8 KB contiguous
// per channel step per block, but 55 warps/SM (86% occ) instead of 27.
// Plain compiler-batched __ldcs loop (best measured form), __stcs stores,
// fast-math sigmoid.
// ---------------------------------------------------------------------------
__global__ __launch_bounds__(512) void weight_kernel(const float* __restrict__ ref,
                                                     float* __restrict__ out) {
    const int bf = blockIdx.x >> 5;                      // 32 blocks per bf
    const int p  = ((blockIdx.x & 31) << 9) + threadIdx.x;   // 0..16383

    __shared__ float sk[C];
    if (threadIdx.x < C) sk[threadIdx.x] = g_ksum[bf * C + threadIdx.x];
    __syncthreads();

    const float4* __restrict__ base =
        reinterpret_cast<const float4*>(ref) + (size_t)bf * C * HW4 + p;

    float ax = 0.f, ay = 0.f, az = 0.f, aw = 0.f;

    #pragma unroll
    for (int c = 0; c < C; c++) {
        float4 v = __ldcs(base + (size_t)c * HW4);
        const float k = sk[c];
        ax = fmaf(v.x, k, ax);
        ay = fmaf(v.y, k, ay);
        az = fmaf(v.z, k, az);
        aw = fmaf(v.w, k, aw);
    }

    float4 r;
    r.x = __fdividef(1.0f, 1.0f + __expf(-ax));
    r.y = __fdividef(1.0f, 1.0f + __expf(-ay));
    r.z = __fdividef(1.0f, 1.0f + __expf(-az));
    r.w = __fdividef(1.0f, 1.0f + __expf(-aw));

    __stcs(reinterpret_cast<float4*>(out) + (size_t)bf * HW4 + p, r);
}

// ---------------------------------------------------------------------------
extern "C" void kernel_launch(void* const* d_in, const int* in_sizes, int n_in,
                              void* d_out, int out_size) {
    const float* nbr = (const float*)d_in[0];
    const float* ref = (const float*)d_in[1];
    float* out = (float*)d_out;

    ksum_kernel<<<BF * C, 256>>>(nbr);
    weight_kernel<<<BF * HW4 / 512, 512>>>(ref, out);
}

// round 10
// speedup vs baseline: 1.0142x; 1.0023x over previous
#include <cuda_runtime.h>
#include <cuda_bf16.h>
#include <math.h>

// Problem: b=2, f=8, c=64, h=w=256  (fp32)
//   k_sum[bf,c] = sum_{hw} nbr[bf,c,hw]
//   out[bf,hw]  = sigmoid( sum_c ref[bf,c,hw] * k_sum[bf,c] )
// HBM streaming: 2 x 268MB reads + 4MB write.
// R9: weight 42.7us @6.38TB/s (512x512, float4, high occ). This round:
// 256-bit loads (ld.global.cs.v8.f32, Blackwell LDG.E.256) in both kernels
// to halve request count per byte.

#define BF     16          // b*f
#define C      64
#define HW     65536       // 256*256
#define HW4    16384       // HW / 4
#define HW8    8192        // HW / 8

// 256-bit streaming load: 8 floats, 32B-aligned.
__device__ __forceinline__ void ldcs_v8(const float* __restrict__ p,
                                        float& a, float& b, float& c, float& d,
                                        float& e, float& f, float& g, float& h) {
    asm volatile("ld.global.cs.v8.f32 {%0,%1,%2,%3,%4,%5,%6,%7}, [%8];"
                 : "=f"(a), "=f"(b), "=f"(c), "=f"(d),
                   "=f"(e), "=f"(f), "=f"(g), "=f"(h)
                 : "l"(p));
}

__device__ float g_ksum[BF * C];

// ---------------------------------------------------------------------------
// Kernel 1: per-channel-plane reduction. One block per (bf,c) plane (256 KB
// contiguous). 256 threads * 32 v8 loads each (was 64 float4 loads).
// ---------------------------------------------------------------------------
__global__ __launch_bounds__(256) void ksum_kernel(const float* __restrict__ nbr) {
    const int ch = blockIdx.x;                       // 0..1023 == bf*64 + c
    const float* __restrict__ p = nbr + (size_t)ch * HW;

    float s = 0.0f;
    #pragma unroll 4
    for (int i = threadIdx.x; i < HW8; i += 256) {
        float a, b, c, d, e, f, g, h;
        ldcs_v8(p + (size_t)i * 8, a, b, c, d, e, f, g, h);
        s += ((a + b) + (c + d)) + ((e + f) + (g + h));
    }

    #pragma unroll
    for (int off = 16; off > 0; off >>= 1)
        s += __shfl_xor_sync(0xffffffffu, s, off);

    __shared__ float warp_sums[8];
    const int lane = threadIdx.x & 31;
    const int wid  = threadIdx.x >> 5;
    if (lane == 0) warp_sums[wid] = s;
    __syncthreads();

    if (wid == 0) {
        float t = (lane < 8) ? warp_sums[lane] : 0.0f;
        #pragma unroll
        for (int off = 4; off > 0; off >>= 1)
            t += __shfl_xor_sync(0xffffffffu, t, off);
        if (lane == 0) g_ksum[ch] = t;
    }
}

// ---------------------------------------------------------------------------
// Kernel 2: weighted channel contraction + sigmoid.
// 512 blocks x 256 threads, ONE v8 (32B) load per thread per channel ->
// same 8 KB contiguous window per channel step, half the LDG count of R9.
// __stcs stores, fast-math sigmoid.
// ---------------------------------------------------------------------------
__global__ __launch_bounds__(256) void weight_kernel(const float* __restrict__ ref,
                                                     float* __restrict__ out) {
    const int bf  = blockIdx.x >> 5;                     // 32 blocks per bf
    const int win = (blockIdx.x & 31) << 11;             // window base (floats)
    const int p   = win + threadIdx.x * 8;               // float index in plane

    __shared__ float sk[C];
    if (threadIdx.x < C) sk[threadIdx.x] = g_ksum[bf * C + threadIdx.x];
    __syncthreads();

    const float* __restrict__ base = ref + (size_t)bf * C * HW + p;

    float a0 = 0.f, a1 = 0.f, a2 = 0.f, a3 = 0.f;
    float a4 = 0.f, a5 = 0.f, a6 = 0.f, a7 = 0.f;

    #pragma unroll
    for (int c = 0; c < C; c++) {
        float v0, v1, v2, v3, v4, v5, v6, v7;
        ldcs_v8(base + (size_t)c * HW, v0, v1, v2, v3, v4, v5, v6, v7);
        const float k = sk[c];
        a0 = fmaf(v0, k, a0);
        a1 = fmaf(v1, k, a1);
        a2 = fmaf(v2, k, a2);
        a3 = fmaf(v3, k, a3);
        a4 = fmaf(v4, k, a4);
        a5 = fmaf(v5, k, a5);
        a6 = fmaf(v6, k, a6);
        a7 = fmaf(v7, k, a7);
    }

    float4 r0, r1;
    r0.x = __fdividef(1.0f, 1.0f + __expf(-a0));
    r0.y = __fdividef(1.0f, 1.0f + __expf(-a1));
    r0.z = __fdividef(1.0f, 1.0f + __expf(-a2));
    r0.w = __fdividef(1.0f, 1.0f + __expf(-a3));
    r1.x = __fdividef(1.0f, 1.0f + __expf(-a4));
    r1.y = __fdividef(1.0f, 1.0f + __expf(-a5));
    r1.z = __fdividef(1.0f, 1.0f + __expf(-a6));
    r1.w = __fdividef(1.0f, 1.0f + __expf(-a7));

    float4* o = reinterpret_cast<float4*>(out + (size_t)bf * HW + p);
    __stcs(o,     r0);
    __stcs(o + 1, r1);
}

// ---------------------------------------------------------------------------
extern "C" void kernel_launch(void* const* d_in, const int* in_sizes, int n_in,
                              void* d_out, int out_size) {
    const float* nbr = (const float*)d_in[0];
    const float* ref = (const float*)d_in[1];
    float* out = (float*)d_out;

    ksum_kernel<<<BF * C, 256>>>(nbr);
    weight_kernel<<<BF * HW / 2048, 256>>>(ref, out);
}